// round 7
// baseline (speedup 1.0000x reference)
#include <cuda_runtime.h>
#include <cuda_fp16.h>
#include <math.h>

// PixelCNN fused forward.
// R7: conv1 scalar FFMA2 (as R6) -> writes relu(h1) as fp16 hi/lo directly
//     into an MMA-ready A matrix (m = h1row*66+col, K=16 ic).
//     conv2 (+b2, relu) + conv3 (+sigmoid) via mma.sync.m16n8k16 f16/f32,
//     3-term hi/lo split for fp32-grade precision. Taps = A-row shifts.

#define IMG_H 64
#define IMG_W 64
#define NCH   16
#define TH    8
#define XR    (TH + 4)
#define XC    (IMG_W + 8)
#define AROWS 596          // 9*66 = 594 used + 2 pad (read up to row 594)

typedef unsigned long long u64;

struct PackedW {
    ulonglong2 w1t[24][4];    // [tap][ocgroup] fp32 pairs
    ulonglong2 w2[16][5][4];  // [ic][tap][ocgroup] fp32
    u64   b1[8];
    u64   b2[8];
    float w3[16];
    float b3;
    float pad[3];
};

__device__   PackedW g_w;
__constant__ PackedW c_w;

__device__ __forceinline__ u64 ffma2(u64 a, u64 b, u64 c) {
    u64 d;
    asm("fma.rn.f32x2 %0, %1, %2, %3;" : "=l"(d) : "l"(a), "l"(b), "l"(c));
    return d;
}
__device__ __forceinline__ u64 dup2(float x) {
    u64 d;
    asm("mov.b64 %0, {%1, %1};" : "=l"(d) : "f"(x));
    return d;
}
__device__ __forceinline__ float2 unpack2(u64 v) {
    float2 r;
    asm("mov.b64 {%0, %1}, %2;" : "=f"(r.x), "=f"(r.y) : "l"(v));
    return r;
}
__device__ __forceinline__ unsigned smem_u32(const void* p) {
    unsigned a;
    asm("{ .reg .u64 t; cvta.to.shared.u64 t, %1; cvt.u32.u64 %0, t; }"
        : "=r"(a) : "l"(p));
    return a;
}
__device__ __forceinline__ void ldsm_x4(unsigned addr, unsigned& r0, unsigned& r1,
                                        unsigned& r2, unsigned& r3) {
    asm volatile("ldmatrix.sync.aligned.m8n8.x4.shared.b16 {%0,%1,%2,%3}, [%4];"
                 : "=r"(r0), "=r"(r1), "=r"(r2), "=r"(r3) : "r"(addr));
}
__device__ __forceinline__ void ldsm_x4t(unsigned addr, unsigned& r0, unsigned& r1,
                                         unsigned& r2, unsigned& r3) {
    asm volatile("ldmatrix.sync.aligned.m8n8.x4.trans.shared.b16 {%0,%1,%2,%3}, [%4];"
                 : "=r"(r0), "=r"(r1), "=r"(r2), "=r"(r3) : "r"(addr));
}
__device__ __forceinline__ void mma16816(float& d0, float& d1, float& d2, float& d3,
                                         unsigned a0, unsigned a1, unsigned a2, unsigned a3,
                                         unsigned b0, unsigned b1) {
    asm volatile(
        "mma.sync.aligned.m16n8k16.row.col.f32.f16.f16.f32 "
        "{%0,%1,%2,%3}, {%4,%5,%6,%7}, {%8,%9}, {%0,%1,%2,%3};"
        : "+f"(d0), "+f"(d1), "+f"(d2), "+f"(d3)
        : "r"(a0), "r"(a1), "r"(a2), "r"(a3), "r"(b0), "r"(b1));
}

// ---- prep: pack masked weights into g_w (float view) ----
__global__ void pixelcnn_prep(const float* __restrict__ w1, const float* __restrict__ b1,
                              const float* __restrict__ w2, const float* __restrict__ b2,
                              const float* __restrict__ w3, const float* __restrict__ b3)
{
    float* dst = reinterpret_cast<float*>(&g_w);
    const int tid = threadIdx.x;

    for (int idx = tid; idx < 24 * NCH; idx += 256) {
        int t = idx / NCH, oc = idx % NCH;
        int ky, kx;
        if (t < 21) { ky = t / 7; kx = t % 7; }
        else        { ky = 3;     kx = t - 21; }
        dst[idx] = w1[oc * 49 + ky * 7 + kx];
    }
    for (int idx = tid; idx < NCH * 5 * NCH; idx += 256) {
        int ic  = idx / (5 * NCH);
        int rem = idx % (5 * NCH);
        int t   = rem / NCH;
        int oc  = rem % NCH;
        int ky, kx;
        if (t < 3) { ky = 0; kx = t; }
        else       { ky = 1; kx = t - 3; }
        dst[384 + idx] = w2[((oc * NCH + ic) * 3 + ky) * 3 + kx];
    }
    if (tid < NCH) {
        dst[1664 + tid] = b1[tid];
        dst[1680 + tid] = b2[tid];
        dst[1696 + tid] = w3[tid];
    }
    if (tid == 0) dst[1712] = b3[0];
}

__global__ __launch_bounds__(256, 4)
void pixelcnn_fused(const float* __restrict__ x, float* __restrict__ out)
{
    __shared__ __align__(16) float   sx[XR][XC];        // 12 x 72 = 3456 B
    __shared__ __align__(16) __half  Ahi[AROWS][16];    // 19072 B
    __shared__ __align__(16) __half  Alo[AROWS][16];    // 19072 B
    __shared__ __align__(16) __half  Bh[5][16][16];     // [tap][ic(k)][oc(n)] 2560 B
    __shared__ __align__(16) __half  Bl[5][16][16];     // 2560 B

    const int tid  = threadIdx.x;
    const int lane = tid & 31;
    const int wid  = tid >> 5;
    const int img  = blockIdx.y;
    const int r0   = blockIdx.x * TH;
    const float* __restrict__ xim = x + img * (IMG_H * IMG_W);
    const float* cwf = reinterpret_cast<const float*>(&c_w);

    // ---- load x halo tile (zero padded) ----
    for (int idx = tid; idx < XR * XC; idx += 256) {
        int i = idx / XC, j = idx % XC;
        int gr = r0 - 4 + i;
        int gc = j - 4;
        float v = 0.0f;
        if (gr >= 0 && gr < IMG_H && gc >= 0 && gc < IMG_W)
            v = xim[gr * IMG_W + gc];
        sx[i][j] = v;
    }

    // ---- build conv2 B matrices (hi/lo f16) from constant ----
    for (int idx = tid; idx < 16 * 5 * 16; idx += 256) {
        int ic  = idx / 80;
        int rem = idx % 80;
        int t   = rem / 16;
        int oc  = rem % 16;
        float v = cwf[384 + ic * 80 + t * 16 + oc];
        __half hi = __float2half_rn(v);
        __half lo = __float2half_rn(v - __half2float(hi));
        Bh[t][ic][oc] = hi;
        Bl[t][ic][oc] = lo;
    }

    // ---- zero A pad rows (594, 595) ----
    if (tid < 16) {
        int rr = 594 + (tid >> 3);
        int cc = (tid & 7) * 2;
        *reinterpret_cast<unsigned*>(&Ahi[rr][cc]) = 0u;
        *reinterpret_cast<unsigned*>(&Alo[rr][cc]) = 0u;
    }
    __syncthreads();

    // ---- conv1 (FFMA2, oc in two halves): 198 threads, 3 h1 columns each ----
    if (tid < 9 * 22) {
        const int hr  = tid / 22;        // sh1 row 0..8  (h1 row r0-1+hr)
        const int hc0 = (tid % 22) * 3;  // col-tilde 0..63 (covers hc0..hc0+2)

        const int grow = r0 - 1 + hr;
        const bool rowok = (grow >= 0);
        const bool okc[3] = { rowok && (hc0 - 1 >= 0),
                              rowok,
                              rowok && (hc0 + 1 < IMG_W) };

        #pragma unroll
        for (int h = 0; h < 2; h++) {           // oc half: channels 8h..8h+7
            u64 acc[3][4];
            #pragma unroll
            for (int q = 0; q < 4; q++) {
                u64 bp = c_w.b1[h * 4 + q];
                acc[0][q] = bp; acc[1][q] = bp; acc[2][q] = bp;
            }

            u64 d[9];
            #pragma unroll
            for (int ky = 0; ky < 3; ky++) {
                #pragma unroll
                for (int k = 0; k < 9; k++) d[k] = dup2(sx[hr + ky][hc0 + k]);
                #pragma unroll
                for (int kx = 0; kx < 7; kx++) {
                    const int t = ky * 7 + kx;
                    #pragma unroll
                    for (int og = 0; og < 2; og++) {
                        ulonglong2 w = c_w.w1t[t][h * 2 + og];
                        const int o = og * 2;
                        acc[0][o + 0] = ffma2(w.x, d[kx + 0], acc[0][o + 0]);
                        acc[1][o + 0] = ffma2(w.x, d[kx + 1], acc[1][o + 0]);
                        acc[2][o + 0] = ffma2(w.x, d[kx + 2], acc[2][o + 0]);
                        acc[0][o + 1] = ffma2(w.y, d[kx + 0], acc[0][o + 1]);
                        acc[1][o + 1] = ffma2(w.y, d[kx + 1], acc[1][o + 1]);
                        acc[2][o + 1] = ffma2(w.y, d[kx + 2], acc[2][o + 1]);
                    }
                }
            }
            {
                #pragma unroll
                for (int k = 0; k < 5; k++) d[k] = dup2(sx[hr + 3][hc0 + k]);
                #pragma unroll
                for (int kx = 0; kx < 3; kx++) {
                    const int t = 21 + kx;
                    #pragma unroll
                    for (int og = 0; og < 2; og++) {
                        ulonglong2 w = c_w.w1t[t][h * 2 + og];
                        const int o = og * 2;
                        acc[0][o + 0] = ffma2(w.x, d[kx + 0], acc[0][o + 0]);
                        acc[1][o + 0] = ffma2(w.x, d[kx + 1], acc[1][o + 0]);
                        acc[2][o + 0] = ffma2(w.x, d[kx + 2], acc[2][o + 0]);
                        acc[0][o + 1] = ffma2(w.y, d[kx + 0], acc[0][o + 1]);
                        acc[1][o + 1] = ffma2(w.y, d[kx + 1], acc[1][o + 1]);
                        acc[2][o + 1] = ffma2(w.y, d[kx + 2], acc[2][o + 1]);
                    }
                }
            }

            // store relu(h1) as fp16 hi/lo pairs into A[m][ic]
            #pragma unroll
            for (int p = 0; p < 3; p++) {
                const int m = hr * 66 + hc0 + p;
                #pragma unroll
                for (int q = 0; q < 4; q++) {
                    float2 v = unpack2(acc[p][q]);
                    float a0 = okc[p] ? fmaxf(v.x, 0.0f) : 0.0f;
                    float a1 = okc[p] ? fmaxf(v.y, 0.0f) : 0.0f;
                    float2 vm = make_float2(a0, a1);
                    __half2 hh = __float22half2_rn(vm);
                    float2 back = __half22float2(hh);
                    __half2 hl = __float22half2_rn(
                        make_float2(vm.x - back.x, vm.y - back.y));
                    *reinterpret_cast<unsigned*>(&Ahi[m][h * 8 + q * 2]) =
                        *reinterpret_cast<unsigned*>(&hh);
                    *reinterpret_cast<unsigned*>(&Alo[m][h * 8 + q * 2]) =
                        *reinterpret_cast<unsigned*>(&hl);
                }
            }
        }
    }
    __syncthreads();

    // ---- conv2 via mma.m16n8k16 (3-term hi/lo) + conv3 + sigmoid ----
    {
        const unsigned ahi_b = smem_u32(&Ahi[0][0]);
        const unsigned alo_b = smem_u32(&Alo[0][0]);
        const unsigned bh_b  = smem_u32(&Bh[0][0][0]);
        const unsigned bl_b  = smem_u32(&Bl[0][0][0]);

        // per-lane ldmatrix address components
        const unsigned arow  = lane & 15;              // row within tile
        const unsigned akoff = (lane >> 4) * 16;       // k-half byte offset (8 halves)
        const unsigned brow  = lane & 15;              // k row
        const unsigned bnoff = (lane >> 4) * 16;       // n-half byte offset

        // cached epilogue constants (cols owned by this lane)
        const int cb = (lane & 3) * 2;
        float b2c[4], w3c[4];
        #pragma unroll
        for (int j = 0; j < 2; j++) {
            b2c[j]     = cwf[1680 + cb + j];
            b2c[2 + j] = cwf[1680 + cb + 8 + j];
            w3c[j]     = cwf[1696 + cb + j];
            w3c[2 + j] = cwf[1696 + cb + 8 + j];
        }
        const float b3v = cwf[1712];

        const int shifts[5] = {0, 1, 2, 66, 67};

        for (int tile = wid; tile < 33; tile += 8) {
            const int m0 = tile * 16;
            float d0[4] = {0.f, 0.f, 0.f, 0.f};   // n-half 0
            float d1[4] = {0.f, 0.f, 0.f, 0.f};   // n-half 1

            #pragma unroll
            for (int t = 0; t < 5; t++) {
                const unsigned rbyte = (unsigned)(m0 + shifts[t] + arow) * 32 + akoff;
                unsigned ah0, ah1, ah2, ah3, al0, al1, al2, al3;
                ldsm_x4(ahi_b + rbyte, ah0, ah1, ah2, ah3);
                ldsm_x4(alo_b + rbyte, al0, al1, al2, al3);

                const unsigned bbyte = (unsigned)t * 512 + brow * 32 + bnoff;
                unsigned bh0, bh1, bh2, bh3, bl0, bl1, bl2, bl3;
                ldsm_x4t(bh_b + bbyte, bh0, bh1, bh2, bh3);
                ldsm_x4t(bl_b + bbyte, bl0, bl1, bl2, bl3);

                // term Ah*Bh
                mma16816(d0[0], d0[1], d0[2], d0[3], ah0, ah1, ah2, ah3, bh0, bh1);
                mma16816(d1[0], d1[1], d1[2], d1[3], ah0, ah1, ah2, ah3, bh2, bh3);
                // term Ah*Bl
                mma16816(d0[0], d0[1], d0[2], d0[3], ah0, ah1, ah2, ah3, bl0, bl1);
                mma16816(d1[0], d1[1], d1[2], d1[3], ah0, ah1, ah2, ah3, bl2, bl3);
                // term Al*Bh
                mma16816(d0[0], d0[1], d0[2], d0[3], al0, al1, al2, al3, bh0, bh1);
                mma16816(d1[0], d1[1], d1[2], d1[3], al0, al1, al2, al3, bh2, bh3);
            }

            // epilogue: h2 = relu(d + b2); z = sum w3*h2; sigmoid
            // d layout: d[0],d[1] -> row g=lane/4, cols cb,cb+1 (n-half adds +8)
            //           d[2],d[3] -> row g+8
            float zA = 0.f, zB = 0.f;
            #pragma unroll
            for (int j = 0; j < 2; j++) {
                zA += fmaxf(d0[j]     + b2c[j],     0.0f) * w3c[j];
                zA += fmaxf(d1[j]     + b2c[2 + j], 0.0f) * w3c[2 + j];
                zB += fmaxf(d0[2 + j] + b2c[j],     0.0f) * w3c[j];
                zB += fmaxf(d1[2 + j] + b2c[2 + j], 0.0f) * w3c[2 + j];
            }
            zA += __shfl_xor_sync(0xffffffffu, zA, 1);
            zA += __shfl_xor_sync(0xffffffffu, zA, 2);
            zB += __shfl_xor_sync(0xffffffffu, zB, 1);
            zB += __shfl_xor_sync(0xffffffffu, zB, 2);

            if ((lane & 3) == 0) {
                const int g = lane >> 2;
                #pragma unroll
                for (int s = 0; s < 2; s++) {
                    const int m = m0 + g + s * 8;
                    const float z = (s == 0 ? zA : zB) + b3v;
                    const int r = m / 66;
                    const int c = m - r * 66;
                    if (c < 64 && r < 8) {
                        float y = 1.0f / (1.0f + __expf(-z));
                        out[img * (IMG_H * IMG_W) + (r0 + r) * IMG_W + c] = y;
                    }
                }
            }
        }
    }
}

extern "C" void kernel_launch(void* const* d_in, const int* in_sizes, int n_in,
                              void* d_out, int out_size) {
    const float* x  = (const float*)d_in[0];
    const float* w1 = (const float*)d_in[1];
    const float* b1 = (const float*)d_in[2];
    const float* w2 = (const float*)d_in[3];
    const float* b2 = (const float*)d_in[4];
    const float* w3 = (const float*)d_in[5];
    const float* b3 = (const float*)d_in[6];
    float* out = (float*)d_out;

    cudaFuncSetAttribute(pixelcnn_fused,
                         cudaFuncAttributePreferredSharedMemoryCarveout, 100);

    pixelcnn_prep<<<1, 256>>>(w1, b1, w2, b2, w3, b3);

    void* g_addr = nullptr;
    cudaGetSymbolAddress(&g_addr, g_w);
    cudaMemcpyToSymbolAsync(c_w, g_addr, sizeof(PackedW), 0,
                            cudaMemcpyDeviceToDevice, 0);

    dim3 grid(IMG_H / TH, 1024);
    pixelcnn_fused<<<grid, 256>>>(x, out);
}

// round 8
// speedup vs baseline: 1.0489x; 1.0489x over previous
#include <cuda_runtime.h>
#include <cuda_fp16.h>
#include <math.h>

// PixelCNN fused forward.
// R8: conv1 scalar FFMA2 -> A matrix (fp16 hi/lo, STS.128 stores);
//     conv2+conv3 via mma.m16n8k16, B fragments hoisted out of tile loop
//     (tile-invariant), 3-term hi/lo split for fp32-grade precision.

#define IMG_H 64
#define IMG_W 64
#define NCH   16
#define TH    8
#define XR    (TH + 4)
#define XC    (IMG_W + 8)
#define AROWS 596          // 9*66 = 594 used + 2 pad

typedef unsigned long long u64;

struct PackedW {
    ulonglong2 w1t[24][4];    // [tap][ocgroup] fp32 pairs
    ulonglong2 w2[16][5][4];  // [ic][tap][ocgroup] fp32
    u64   b1[8];
    u64   b2[8];
    float w3[16];
    float b3;
    float pad[3];
};

__device__   PackedW g_w;
__constant__ PackedW c_w;

__device__ __forceinline__ u64 ffma2(u64 a, u64 b, u64 c) {
    u64 d;
    asm("fma.rn.f32x2 %0, %1, %2, %3;" : "=l"(d) : "l"(a), "l"(b), "l"(c));
    return d;
}
__device__ __forceinline__ u64 dup2(float x) {
    u64 d;
    asm("mov.b64 %0, {%1, %1};" : "=l"(d) : "f"(x));
    return d;
}
__device__ __forceinline__ float2 unpack2(u64 v) {
    float2 r;
    asm("mov.b64 {%0, %1}, %2;" : "=f"(r.x), "=f"(r.y) : "l"(v));
    return r;
}
__device__ __forceinline__ unsigned smem_u32(const void* p) {
    unsigned a;
    asm("{ .reg .u64 t; cvta.to.shared.u64 t, %1; cvt.u32.u64 %0, t; }"
        : "=r"(a) : "l"(p));
    return a;
}
__device__ __forceinline__ void ldsm_x4(unsigned addr, unsigned& r0, unsigned& r1,
                                        unsigned& r2, unsigned& r3) {
    asm volatile("ldmatrix.sync.aligned.m8n8.x4.shared.b16 {%0,%1,%2,%3}, [%4];"
                 : "=r"(r0), "=r"(r1), "=r"(r2), "=r"(r3) : "r"(addr));
}
__device__ __forceinline__ void ldsm_x4t(unsigned addr, unsigned& r0, unsigned& r1,
                                         unsigned& r2, unsigned& r3) {
    asm volatile("ldmatrix.sync.aligned.m8n8.x4.trans.shared.b16 {%0,%1,%2,%3}, [%4];"
                 : "=r"(r0), "=r"(r1), "=r"(r2), "=r"(r3) : "r"(addr));
}
__device__ __forceinline__ void mma16816(float& d0, float& d1, float& d2, float& d3,
                                         unsigned a0, unsigned a1, unsigned a2, unsigned a3,
                                         unsigned b0, unsigned b1) {
    asm volatile(
        "mma.sync.aligned.m16n8k16.row.col.f32.f16.f16.f32 "
        "{%0,%1,%2,%3}, {%4,%5,%6,%7}, {%8,%9}, {%0,%1,%2,%3};"
        : "+f"(d0), "+f"(d1), "+f"(d2), "+f"(d3)
        : "r"(a0), "r"(a1), "r"(a2), "r"(a3), "r"(b0), "r"(b1));
}

// ---- prep: pack masked weights into g_w (float view) ----
__global__ void pixelcnn_prep(const float* __restrict__ w1, const float* __restrict__ b1,
                              const float* __restrict__ w2, const float* __restrict__ b2,
                              const float* __restrict__ w3, const float* __restrict__ b3)
{
    float* dst = reinterpret_cast<float*>(&g_w);
    const int tid = threadIdx.x;

    for (int idx = tid; idx < 24 * NCH; idx += 256) {
        int t = idx / NCH, oc = idx % NCH;
        int ky, kx;
        if (t < 21) { ky = t / 7; kx = t % 7; }
        else        { ky = 3;     kx = t - 21; }
        dst[idx] = w1[oc * 49 + ky * 7 + kx];
    }
    for (int idx = tid; idx < NCH * 5 * NCH; idx += 256) {
        int ic  = idx / (5 * NCH);
        int rem = idx % (5 * NCH);
        int t   = rem / NCH;
        int oc  = rem % NCH;
        int ky, kx;
        if (t < 3) { ky = 0; kx = t; }
        else       { ky = 1; kx = t - 3; }
        dst[384 + idx] = w2[((oc * NCH + ic) * 3 + ky) * 3 + kx];
    }
    if (tid < NCH) {
        dst[1664 + tid] = b1[tid];
        dst[1680 + tid] = b2[tid];
        dst[1696 + tid] = w3[tid];
    }
    if (tid == 0) dst[1712] = b3[0];
}

__global__ __launch_bounds__(256, 3)
void pixelcnn_fused(const float* __restrict__ x, float* __restrict__ out)
{
    __shared__ __align__(16) float   sx[XR][XC];        // 3456 B
    __shared__ __align__(16) __half  Ahi[AROWS][16];    // 19072 B
    __shared__ __align__(16) __half  Alo[AROWS][16];    // 19072 B
    __shared__ __align__(16) __half  Bh[5][16][16];     // 2560 B
    __shared__ __align__(16) __half  Bl[5][16][16];     // 2560 B

    const int tid  = threadIdx.x;
    const int lane = tid & 31;
    const int wid  = tid >> 5;
    const int img  = blockIdx.y;
    const int r0   = blockIdx.x * TH;
    const float* __restrict__ xim = x + img * (IMG_H * IMG_W);
    const float* cwf = reinterpret_cast<const float*>(&c_w);

    // ---- load x halo tile (zero padded) ----
    for (int idx = tid; idx < XR * XC; idx += 256) {
        int i = idx / XC, j = idx % XC;
        int gr = r0 - 4 + i;
        int gc = j - 4;
        float v = 0.0f;
        if (gr >= 0 && gr < IMG_H && gc >= 0 && gc < IMG_W)
            v = xim[gr * IMG_W + gc];
        sx[i][j] = v;
    }

    // ---- build conv2 B matrices (hi/lo f16) ----
    for (int idx = tid; idx < 16 * 5 * 16; idx += 256) {
        int ic  = idx / 80;
        int rem = idx % 80;
        int t   = rem / 16;
        int oc  = rem % 16;
        float v = cwf[384 + ic * 80 + t * 16 + oc];
        __half hi = __float2half_rn(v);
        __half lo = __float2half_rn(v - __half2float(hi));
        Bh[t][ic][oc] = hi;
        Bl[t][ic][oc] = lo;
    }

    // ---- zero A pad rows (594, 595) ----
    if (tid < 16) {
        int rr = 594 + (tid >> 3);
        int cc = (tid & 7) * 2;
        *reinterpret_cast<unsigned*>(&Ahi[rr][cc]) = 0u;
        *reinterpret_cast<unsigned*>(&Alo[rr][cc]) = 0u;
    }
    __syncthreads();

    // ---- conv1 (FFMA2, oc in two halves): 198 threads, 3 h1 columns each ----
    if (tid < 9 * 22) {
        const int hr  = tid / 22;
        const int hc0 = (tid % 22) * 3;

        const int grow = r0 - 1 + hr;
        const bool rowok = (grow >= 0);
        const bool okc[3] = { rowok && (hc0 - 1 >= 0),
                              rowok,
                              rowok && (hc0 + 1 < IMG_W) };

        #pragma unroll
        for (int h = 0; h < 2; h++) {
            u64 acc[3][4];
            #pragma unroll
            for (int q = 0; q < 4; q++) {
                u64 bp = c_w.b1[h * 4 + q];
                acc[0][q] = bp; acc[1][q] = bp; acc[2][q] = bp;
            }

            u64 d[9];
            #pragma unroll
            for (int ky = 0; ky < 3; ky++) {
                #pragma unroll
                for (int k = 0; k < 9; k++) d[k] = dup2(sx[hr + ky][hc0 + k]);
                #pragma unroll
                for (int kx = 0; kx < 7; kx++) {
                    const int t = ky * 7 + kx;
                    #pragma unroll
                    for (int og = 0; og < 2; og++) {
                        ulonglong2 w = c_w.w1t[t][h * 2 + og];
                        const int o = og * 2;
                        acc[0][o + 0] = ffma2(w.x, d[kx + 0], acc[0][o + 0]);
                        acc[1][o + 0] = ffma2(w.x, d[kx + 1], acc[1][o + 0]);
                        acc[2][o + 0] = ffma2(w.x, d[kx + 2], acc[2][o + 0]);
                        acc[0][o + 1] = ffma2(w.y, d[kx + 0], acc[0][o + 1]);
                        acc[1][o + 1] = ffma2(w.y, d[kx + 1], acc[1][o + 1]);
                        acc[2][o + 1] = ffma2(w.y, d[kx + 2], acc[2][o + 1]);
                    }
                }
            }
            {
                #pragma unroll
                for (int k = 0; k < 5; k++) d[k] = dup2(sx[hr + 3][hc0 + k]);
                #pragma unroll
                for (int kx = 0; kx < 3; kx++) {
                    const int t = 21 + kx;
                    #pragma unroll
                    for (int og = 0; og < 2; og++) {
                        ulonglong2 w = c_w.w1t[t][h * 2 + og];
                        const int o = og * 2;
                        acc[0][o + 0] = ffma2(w.x, d[kx + 0], acc[0][o + 0]);
                        acc[1][o + 0] = ffma2(w.x, d[kx + 1], acc[1][o + 0]);
                        acc[2][o + 0] = ffma2(w.x, d[kx + 2], acc[2][o + 0]);
                        acc[0][o + 1] = ffma2(w.y, d[kx + 0], acc[0][o + 1]);
                        acc[1][o + 1] = ffma2(w.y, d[kx + 1], acc[1][o + 1]);
                        acc[2][o + 1] = ffma2(w.y, d[kx + 2], acc[2][o + 1]);
                    }
                }
            }

            // store relu(h1) as fp16 hi/lo, one STS.128 per (pixel, array)
            #pragma unroll
            for (int p = 0; p < 3; p++) {
                const int m = hr * 66 + hc0 + p;
                unsigned hiw[4], low[4];
                #pragma unroll
                for (int q = 0; q < 4; q++) {
                    float2 v = unpack2(acc[p][q]);
                    float a0 = okc[p] ? fmaxf(v.x, 0.0f) : 0.0f;
                    float a1 = okc[p] ? fmaxf(v.y, 0.0f) : 0.0f;
                    float2 vm = make_float2(a0, a1);
                    __half2 hh = __float22half2_rn(vm);
                    float2 back = __half22float2(hh);
                    __half2 hl = __float22half2_rn(
                        make_float2(vm.x - back.x, vm.y - back.y));
                    hiw[q] = *reinterpret_cast<unsigned*>(&hh);
                    low[q] = *reinterpret_cast<unsigned*>(&hl);
                }
                *reinterpret_cast<uint4*>(&Ahi[m][h * 8]) =
                    make_uint4(hiw[0], hiw[1], hiw[2], hiw[3]);
                *reinterpret_cast<uint4*>(&Alo[m][h * 8]) =
                    make_uint4(low[0], low[1], low[2], low[3]);
            }
        }
    }
    __syncthreads();

    // ---- conv2 via mma (B fragments hoisted) + conv3 + sigmoid ----
    {
        const unsigned ahi_b = smem_u32(&Ahi[0][0]);
        const unsigned alo_b = smem_u32(&Alo[0][0]);
        const unsigned bh_b  = smem_u32(&Bh[0][0][0]);
        const unsigned bl_b  = smem_u32(&Bl[0][0][0]);

        const unsigned arow  = lane & 15;
        const unsigned akoff = (lane >> 4) * 16;
        const unsigned brow  = lane & 15;
        const unsigned bnoff = (lane >> 4) * 16;

        // hoist B fragments: tile-invariant, load once per warp
        unsigned bh[5][4], bl[5][4];
        #pragma unroll
        for (int t = 0; t < 5; t++) {
            const unsigned bbyte = (unsigned)t * 512 + brow * 32 + bnoff;
            ldsm_x4t(bh_b + bbyte, bh[t][0], bh[t][1], bh[t][2], bh[t][3]);
            ldsm_x4t(bl_b + bbyte, bl[t][0], bl[t][1], bl[t][2], bl[t][3]);
        }

        // epilogue constants
        const int cb = (lane & 3) * 2;
        float b2c[4], w3c[4];
        #pragma unroll
        for (int j = 0; j < 2; j++) {
            b2c[j]     = cwf[1680 + cb + j];
            b2c[2 + j] = cwf[1680 + cb + 8 + j];
            w3c[j]     = cwf[1696 + cb + j];
            w3c[2 + j] = cwf[1696 + cb + 8 + j];
        }
        const float b3v = cwf[1712];

        const int shifts[5] = {0, 1, 2, 66, 67};

        for (int tile = wid; tile < 33; tile += 8) {
            const int m0 = tile * 16;
            float d0[4] = {0.f, 0.f, 0.f, 0.f};
            float d1[4] = {0.f, 0.f, 0.f, 0.f};

            #pragma unroll
            for (int t = 0; t < 5; t++) {
                const unsigned rbyte = (unsigned)(m0 + shifts[t] + arow) * 32 + akoff;
                unsigned ah0, ah1, ah2, ah3, al0, al1, al2, al3;
                ldsm_x4(ahi_b + rbyte, ah0, ah1, ah2, ah3);
                ldsm_x4(alo_b + rbyte, al0, al1, al2, al3);

                mma16816(d0[0], d0[1], d0[2], d0[3], ah0, ah1, ah2, ah3, bh[t][0], bh[t][1]);
                mma16816(d1[0], d1[1], d1[2], d1[3], ah0, ah1, ah2, ah3, bh[t][2], bh[t][3]);
                mma16816(d0[0], d0[1], d0[2], d0[3], ah0, ah1, ah2, ah3, bl[t][0], bl[t][1]);
                mma16816(d1[0], d1[1], d1[2], d1[3], ah0, ah1, ah2, ah3, bl[t][2], bl[t][3]);
                mma16816(d0[0], d0[1], d0[2], d0[3], al0, al1, al2, al3, bh[t][0], bh[t][1]);
                mma16816(d1[0], d1[1], d1[2], d1[3], al0, al1, al2, al3, bh[t][2], bh[t][3]);
            }

            float zA = 0.f, zB = 0.f;
            #pragma unroll
            for (int j = 0; j < 2; j++) {
                zA += fmaxf(d0[j]     + b2c[j],     0.0f) * w3c[j];
                zA += fmaxf(d1[j]     + b2c[2 + j], 0.0f) * w3c[2 + j];
                zB += fmaxf(d0[2 + j] + b2c[j],     0.0f) * w3c[j];
                zB += fmaxf(d1[2 + j] + b2c[2 + j], 0.0f) * w3c[2 + j];
            }
            zA += __shfl_xor_sync(0xffffffffu, zA, 1);
            zA += __shfl_xor_sync(0xffffffffu, zA, 2);
            zB += __shfl_xor_sync(0xffffffffu, zB, 1);
            zB += __shfl_xor_sync(0xffffffffu, zB, 2);

            if ((lane & 3) == 0) {
                const int g = lane >> 2;
                #pragma unroll
                for (int s = 0; s < 2; s++) {
                    const int m = m0 + g + s * 8;
                    const float z = (s == 0 ? zA : zB) + b3v;
                    const int r = m / 66;
                    const int c = m - r * 66;
                    if (c < 64 && r < 8) {
                        float y = 1.0f / (1.0f + __expf(-z));
                        out[img * (IMG_H * IMG_W) + (r0 + r) * IMG_W + c] = y;
                    }
                }
            }
        }
    }
}

extern "C" void kernel_launch(void* const* d_in, const int* in_sizes, int n_in,
                              void* d_out, int out_size) {
    const float* x  = (const float*)d_in[0];
    const float* w1 = (const float*)d_in[1];
    const float* b1 = (const float*)d_in[2];
    const float* w2 = (const float*)d_in[3];
    const float* b2 = (const float*)d_in[4];
    const float* w3 = (const float*)d_in[5];
    const float* b3 = (const float*)d_in[6];
    float* out = (float*)d_out;

    cudaFuncSetAttribute(pixelcnn_fused,
                         cudaFuncAttributePreferredSharedMemoryCarveout, 100);

    pixelcnn_prep<<<1, 256>>>(w1, b1, w2, b2, w3, b3);

    void* g_addr = nullptr;
    cudaGetSymbolAddress(&g_addr, g_w);
    cudaMemcpyToSymbolAsync(c_w, g_addr, sizeof(PackedW), 0,
                            cudaMemcpyDeviceToDevice, 0);

    dim3 grid(IMG_H / TH, 1024);
    pixelcnn_fused<<<grid, 256>>>(x, out);
}

// round 9
// speedup vs baseline: 1.0923x; 1.0414x over previous
#include <cuda_runtime.h>
#include <cuda_fp16.h>
#include <math.h>

// PixelCNN fused forward.
// R9: conv1 scalar FFMA2 on ALL 256 threads (1 pass over 16 oc, pixels
//     strided by 256); conv2+conv3 via mma.m16n8k16 with hoisted B frags,
//     3-term hi/lo split. 4 CTAs/SM reg cap.

#define IMG_H 64
#define IMG_W 64
#define NCH   16
#define TH    8
#define XR    (TH + 4)
#define XC    (IMG_W + 8)
#define AROWS 596          // 9*66 = 594 used + 2 pad

typedef unsigned long long u64;

struct PackedW {
    ulonglong2 w1t[24][4];    // [tap][ocgroup] fp32 pairs
    ulonglong2 w2[16][5][4];  // [ic][tap][ocgroup] fp32
    u64   b1[8];
    u64   b2[8];
    float w3[16];
    float b3;
    float pad[3];
};

__device__   PackedW g_w;
__constant__ PackedW c_w;

__device__ __forceinline__ u64 ffma2(u64 a, u64 b, u64 c) {
    u64 d;
    asm("fma.rn.f32x2 %0, %1, %2, %3;" : "=l"(d) : "l"(a), "l"(b), "l"(c));
    return d;
}
__device__ __forceinline__ u64 dup2(float x) {
    u64 d;
    asm("mov.b64 %0, {%1, %1};" : "=l"(d) : "f"(x));
    return d;
}
__device__ __forceinline__ float2 unpack2(u64 v) {
    float2 r;
    asm("mov.b64 {%0, %1}, %2;" : "=f"(r.x), "=f"(r.y) : "l"(v));
    return r;
}
__device__ __forceinline__ unsigned smem_u32(const void* p) {
    unsigned a;
    asm("{ .reg .u64 t; cvta.to.shared.u64 t, %1; cvt.u32.u64 %0, t; }"
        : "=r"(a) : "l"(p));
    return a;
}
__device__ __forceinline__ void ldsm_x4(unsigned addr, unsigned& r0, unsigned& r1,
                                        unsigned& r2, unsigned& r3) {
    asm volatile("ldmatrix.sync.aligned.m8n8.x4.shared.b16 {%0,%1,%2,%3}, [%4];"
                 : "=r"(r0), "=r"(r1), "=r"(r2), "=r"(r3) : "r"(addr));
}
__device__ __forceinline__ void ldsm_x4t(unsigned addr, unsigned& r0, unsigned& r1,
                                         unsigned& r2, unsigned& r3) {
    asm volatile("ldmatrix.sync.aligned.m8n8.x4.trans.shared.b16 {%0,%1,%2,%3}, [%4];"
                 : "=r"(r0), "=r"(r1), "=r"(r2), "=r"(r3) : "r"(addr));
}
__device__ __forceinline__ void mma16816(float& d0, float& d1, float& d2, float& d3,
                                         unsigned a0, unsigned a1, unsigned a2, unsigned a3,
                                         unsigned b0, unsigned b1) {
    asm volatile(
        "mma.sync.aligned.m16n8k16.row.col.f32.f16.f16.f32 "
        "{%0,%1,%2,%3}, {%4,%5,%6,%7}, {%8,%9}, {%0,%1,%2,%3};"
        : "+f"(d0), "+f"(d1), "+f"(d2), "+f"(d3)
        : "r"(a0), "r"(a1), "r"(a2), "r"(a3), "r"(b0), "r"(b1));
}

// ---- prep: pack masked weights into g_w (float view) ----
__global__ void pixelcnn_prep(const float* __restrict__ w1, const float* __restrict__ b1,
                              const float* __restrict__ w2, const float* __restrict__ b2,
                              const float* __restrict__ w3, const float* __restrict__ b3)
{
    float* dst = reinterpret_cast<float*>(&g_w);
    const int tid = threadIdx.x;

    for (int idx = tid; idx < 24 * NCH; idx += 256) {
        int t = idx / NCH, oc = idx % NCH;
        int ky, kx;
        if (t < 21) { ky = t / 7; kx = t % 7; }
        else        { ky = 3;     kx = t - 21; }
        dst[idx] = w1[oc * 49 + ky * 7 + kx];
    }
    for (int idx = tid; idx < NCH * 5 * NCH; idx += 256) {
        int ic  = idx / (5 * NCH);
        int rem = idx % (5 * NCH);
        int t   = rem / NCH;
        int oc  = rem % NCH;
        int ky, kx;
        if (t < 3) { ky = 0; kx = t; }
        else       { ky = 1; kx = t - 3; }
        dst[384 + idx] = w2[((oc * NCH + ic) * 3 + ky) * 3 + kx];
    }
    if (tid < NCH) {
        dst[1664 + tid] = b1[tid];
        dst[1680 + tid] = b2[tid];
        dst[1696 + tid] = w3[tid];
    }
    if (tid == 0) dst[1712] = b3[0];
}

__global__ __launch_bounds__(256, 4)
void pixelcnn_fused(const float* __restrict__ x, float* __restrict__ out)
{
    __shared__ __align__(16) float   sx[XR][XC];        // 3456 B
    __shared__ __align__(16) __half  Ahi[AROWS][16];    // 19072 B
    __shared__ __align__(16) __half  Alo[AROWS][16];    // 19072 B
    __shared__ __align__(16) __half  Bh[5][16][16];     // 2560 B
    __shared__ __align__(16) __half  Bl[5][16][16];     // 2560 B

    const int tid  = threadIdx.x;
    const int lane = tid & 31;
    const int wid  = tid >> 5;
    const int img  = blockIdx.y;
    const int r0   = blockIdx.x * TH;
    const float* __restrict__ xim = x + img * (IMG_H * IMG_W);
    const float* cwf = reinterpret_cast<const float*>(&c_w);

    // ---- load x halo tile (zero padded) ----
    for (int idx = tid; idx < XR * XC; idx += 256) {
        int i = idx / XC, j = idx % XC;
        int gr = r0 - 4 + i;
        int gc = j - 4;
        float v = 0.0f;
        if (gr >= 0 && gr < IMG_H && gc >= 0 && gc < IMG_W)
            v = xim[gr * IMG_W + gc];
        sx[i][j] = v;
    }

    // ---- build conv2 B matrices (hi/lo f16) ----
    for (int idx = tid; idx < 16 * 5 * 16; idx += 256) {
        int ic  = idx / 80;
        int rem = idx % 80;
        int t   = rem / 16;
        int oc  = rem % 16;
        float v = cwf[384 + ic * 80 + t * 16 + oc];
        __half hi = __float2half_rn(v);
        __half lo = __float2half_rn(v - __half2float(hi));
        Bh[t][ic][oc] = hi;
        Bl[t][ic][oc] = lo;
    }

    // ---- zero A pad rows (594, 595) ----
    if (tid < 16) {
        int rr = 594 + (tid >> 3);
        int cc = (tid & 7) * 2;
        *reinterpret_cast<unsigned*>(&Ahi[rr][cc]) = 0u;
        *reinterpret_cast<unsigned*>(&Alo[rr][cc]) = 0u;
    }
    __syncthreads();

    // ---- conv1: all 256 threads, pixels strided by 256, all 16 oc/pass ----
    for (int m = tid; m < 594; m += 256) {
        const int hr = m / 66;
        const int hc = m - hr * 66;
        const int grow = r0 - 1 + hr;
        const bool ok = (grow >= 0) && (hc >= 1) && (hc < 65);

        u64 acc[8];
        #pragma unroll
        for (int q = 0; q < 8; q++) acc[q] = c_w.b1[q];

        #pragma unroll
        for (int ky = 0; ky < 3; ky++) {
            #pragma unroll
            for (int kx = 0; kx < 7; kx++) {
                const int t = ky * 7 + kx;
                const u64 d = dup2(sx[hr + ky][hc + kx]);
                #pragma unroll
                for (int og = 0; og < 4; og++) {
                    ulonglong2 w = c_w.w1t[t][og];
                    acc[og * 2 + 0] = ffma2(w.x, d, acc[og * 2 + 0]);
                    acc[og * 2 + 1] = ffma2(w.y, d, acc[og * 2 + 1]);
                }
            }
        }
        #pragma unroll
        for (int kx = 0; kx < 3; kx++) {
            const int t = 21 + kx;
            const u64 d = dup2(sx[hr + 3][hc + kx]);
            #pragma unroll
            for (int og = 0; og < 4; og++) {
                ulonglong2 w = c_w.w1t[t][og];
                acc[og * 2 + 0] = ffma2(w.x, d, acc[og * 2 + 0]);
                acc[og * 2 + 1] = ffma2(w.y, d, acc[og * 2 + 1]);
            }
        }

        // relu + mask, split fp16 hi/lo, 4x STS.128
        unsigned hiw[8], low[8];
        #pragma unroll
        for (int q = 0; q < 8; q++) {
            float2 v = unpack2(acc[q]);
            float a0 = ok ? fmaxf(v.x, 0.0f) : 0.0f;
            float a1 = ok ? fmaxf(v.y, 0.0f) : 0.0f;
            float2 vm = make_float2(a0, a1);
            __half2 hh = __float22half2_rn(vm);
            float2 back = __half22float2(hh);
            __half2 hl = __float22half2_rn(
                make_float2(vm.x - back.x, vm.y - back.y));
            hiw[q] = *reinterpret_cast<unsigned*>(&hh);
            low[q] = *reinterpret_cast<unsigned*>(&hl);
        }
        *reinterpret_cast<uint4*>(&Ahi[m][0]) = make_uint4(hiw[0], hiw[1], hiw[2], hiw[3]);
        *reinterpret_cast<uint4*>(&Ahi[m][8]) = make_uint4(hiw[4], hiw[5], hiw[6], hiw[7]);
        *reinterpret_cast<uint4*>(&Alo[m][0]) = make_uint4(low[0], low[1], low[2], low[3]);
        *reinterpret_cast<uint4*>(&Alo[m][8]) = make_uint4(low[4], low[5], low[6], low[7]);
    }
    __syncthreads();

    // ---- conv2 via mma (B fragments hoisted) + conv3 + sigmoid ----
    {
        const unsigned ahi_b = smem_u32(&Ahi[0][0]);
        const unsigned alo_b = smem_u32(&Alo[0][0]);
        const unsigned bh_b  = smem_u32(&Bh[0][0][0]);
        const unsigned bl_b  = smem_u32(&Bl[0][0][0]);

        const unsigned arow  = lane & 15;
        const unsigned akoff = (lane >> 4) * 16;
        const unsigned brow  = lane & 15;
        const unsigned bnoff = (lane >> 4) * 16;

        // hoist B fragments: tile-invariant
        unsigned bh[5][4], bl[5][4];
        #pragma unroll
        for (int t = 0; t < 5; t++) {
            const unsigned bbyte = (unsigned)t * 512 + brow * 32 + bnoff;
            ldsm_x4t(bh_b + bbyte, bh[t][0], bh[t][1], bh[t][2], bh[t][3]);
            ldsm_x4t(bl_b + bbyte, bl[t][0], bl[t][1], bl[t][2], bl[t][3]);
        }

        // epilogue constants
        const int cb = (lane & 3) * 2;
        float b2c[4], w3c[4];
        #pragma unroll
        for (int j = 0; j < 2; j++) {
            b2c[j]     = cwf[1680 + cb + j];
            b2c[2 + j] = cwf[1680 + cb + 8 + j];
            w3c[j]     = cwf[1696 + cb + j];
            w3c[2 + j] = cwf[1696 + cb + 8 + j];
        }
        const float b3v = cwf[1712];

        const int shifts[5] = {0, 1, 2, 66, 67};

        for (int tile = wid; tile < 33; tile += 8) {
            const int m0 = tile * 16;
            float d0[4] = {0.f, 0.f, 0.f, 0.f};
            float d1[4] = {0.f, 0.f, 0.f, 0.f};

            #pragma unroll
            for (int t = 0; t < 5; t++) {
                const unsigned rbyte = (unsigned)(m0 + shifts[t] + arow) * 32 + akoff;
                unsigned ah0, ah1, ah2, ah3, al0, al1, al2, al3;
                ldsm_x4(ahi_b + rbyte, ah0, ah1, ah2, ah3);
                ldsm_x4(alo_b + rbyte, al0, al1, al2, al3);

                mma16816(d0[0], d0[1], d0[2], d0[3], ah0, ah1, ah2, ah3, bh[t][0], bh[t][1]);
                mma16816(d1[0], d1[1], d1[2], d1[3], ah0, ah1, ah2, ah3, bh[t][2], bh[t][3]);
                mma16816(d0[0], d0[1], d0[2], d0[3], ah0, ah1, ah2, ah3, bl[t][0], bl[t][1]);
                mma16816(d1[0], d1[1], d1[2], d1[3], ah0, ah1, ah2, ah3, bl[t][2], bl[t][3]);
                mma16816(d0[0], d0[1], d0[2], d0[3], al0, al1, al2, al3, bh[t][0], bh[t][1]);
                mma16816(d1[0], d1[1], d1[2], d1[3], al0, al1, al2, al3, bh[t][2], bh[t][3]);
            }

            float zA = 0.f, zB = 0.f;
            #pragma unroll
            for (int j = 0; j < 2; j++) {
                zA += fmaxf(d0[j]     + b2c[j],     0.0f) * w3c[j];
                zA += fmaxf(d1[j]     + b2c[2 + j], 0.0f) * w3c[2 + j];
                zB += fmaxf(d0[2 + j] + b2c[j],     0.0f) * w3c[j];
                zB += fmaxf(d1[2 + j] + b2c[2 + j], 0.0f) * w3c[2 + j];
            }
            zA += __shfl_xor_sync(0xffffffffu, zA, 1);
            zA += __shfl_xor_sync(0xffffffffu, zA, 2);
            zB += __shfl_xor_sync(0xffffffffu, zB, 1);
            zB += __shfl_xor_sync(0xffffffffu, zB, 2);

            if ((lane & 3) == 0) {
                const int g = lane >> 2;
                #pragma unroll
                for (int s = 0; s < 2; s++) {
                    const int m = m0 + g + s * 8;
                    const float z = (s == 0 ? zA : zB) + b3v;
                    const int r = m / 66;
                    const int c = m - r * 66;
                    if (c < 64 && r < 8) {
                        float y = 1.0f / (1.0f + __expf(-z));
                        out[img * (IMG_H * IMG_W) + (r0 + r) * IMG_W + c] = y;
                    }
                }
            }
        }
    }
}

extern "C" void kernel_launch(void* const* d_in, const int* in_sizes, int n_in,
                              void* d_out, int out_size) {
    const float* x  = (const float*)d_in[0];
    const float* w1 = (const float*)d_in[1];
    const float* b1 = (const float*)d_in[2];
    const float* w2 = (const float*)d_in[3];
    const float* b2 = (const float*)d_in[4];
    const float* w3 = (const float*)d_in[5];
    const float* b3 = (const float*)d_in[6];
    float* out = (float*)d_out;

    cudaFuncSetAttribute(pixelcnn_fused,
                         cudaFuncAttributePreferredSharedMemoryCarveout, 100);

    pixelcnn_prep<<<1, 256>>>(w1, b1, w2, b2, w3, b3);

    void* g_addr = nullptr;
    cudaGetSymbolAddress(&g_addr, g_w);
    cudaMemcpyToSymbolAsync(c_w, g_addr, sizeof(PackedW), 0,
                            cudaMemcpyDeviceToDevice, 0);

    dim3 grid(IMG_H / TH, 1024);
    pixelcnn_fused<<<grid, 256>>>(x, out);
}